// round 13
// baseline (speedup 1.0000x reference)
#include <cuda_runtime.h>
#include <math.h>
#include <stdint.h>

// ---------------------------------------------------------------------------
// SD_attn_Cross on GB300 (compute_103 => mma.sync tf32 path).
// GEMM: block 128x128, 4 warps (2m x 2n), warp tile 64x64, BK=16,
// 3-stage cp.async ring (single barrier per chunk), ldmatrix A fragments,
// padded conflict-free smem.
// ---------------------------------------------------------------------------

#define TOKENS 65536

__device__ float g_qv[(size_t)TOKENS * 1024];
__device__ float g_k [(size_t)TOKENS * 512];
__device__ float g_o [(size_t)TOKENS * 512];

// ------------------------------ PTX helpers --------------------------------
__device__ __forceinline__ uint32_t smem_u32(const void* p) {
    uint32_t a;
    asm("{ .reg .u64 t; cvta.to.shared.u64 t, %1; cvt.u32.u64 %0, t; }"
        : "=r"(a) : "l"(p));
    return a;
}
#define CP_ASYNC16(sdst, gsrc) \
    asm volatile("cp.async.cg.shared.global [%0], [%1], 16;" :: "r"(sdst), "l"(gsrc) : "memory")
#define CP_COMMIT() asm volatile("cp.async.commit_group;" ::: "memory")

__device__ __forceinline__ uint32_t f2tf32(float x) {
    uint32_t u;
    asm("cvt.rna.tf32.f32 %0, %1;" : "=r"(u) : "f"(x));
    return u;
}
__device__ __forceinline__ void mma_tf32(float c[4], const uint32_t a[4],
                                         const uint32_t b[2]) {
    asm volatile(
        "mma.sync.aligned.m16n8k8.row.col.f32.tf32.tf32.f32 "
        "{%0,%1,%2,%3}, {%4,%5,%6,%7}, {%8,%9}, {%0,%1,%2,%3};"
        : "+f"(c[0]), "+f"(c[1]), "+f"(c[2]), "+f"(c[3])
        : "r"(a[0]), "r"(a[1]), "r"(a[2]), "r"(a[3]), "r"(b[0]), "r"(b[1]));
}
#define LDSM4(r0, r1, r2, r3, addr)                                           \
    asm volatile("ldmatrix.sync.aligned.m8n8.x4.shared.b16 {%0,%1,%2,%3},[%4];" \
                 : "=r"(r0), "=r"(r1), "=r"(r2), "=r"(r3) : "r"(addr))
__device__ __forceinline__ float lds_f32(uint32_t addr) {
    float v;
    asm volatile("ld.shared.f32 %0, [%1];" : "=f"(v) : "r"(addr));
    return v;
}

// ------------------------- tf32 tensor-core GEMM ---------------------------
// C[m,n] = sum_k A[m,k]*B[k,n] + bias[n].  K=512 fixed, M,N multiples of 128.
// Smem stage: A 128 rows x stride 28 fl (112B, 16B-aligned, LDSM-conflict-free)
//             B  16 rows x stride 136 fl (bank g+8t distinct => conflict-free)
#define A_STRIDE 28
#define B_STRIDE 136
#define A_FLOATS (128 * A_STRIDE)              // 3584
#define STG_FLOATS (A_FLOATS + 16 * B_STRIDE)  // 5760
#define STG_BYTES (STG_FLOATS * 4)             // 23040
#define B_OFF_B (A_FLOATS * 4)                 // 14336

__global__ __launch_bounds__(128, 3)
void mm_tf32(const float* __restrict__ A, const float* __restrict__ B,
             const float* __restrict__ bias, float* __restrict__ C, int Ntot) {
    __shared__ __align__(16) float smem_buf[3][STG_FLOATS];

    const int tid  = threadIdx.x;
    const int lane = tid & 31;
    const int wid  = tid >> 5;
    const int g    = lane >> 2;
    const int t    = lane & 3;
    const int wm   = wid & 1;          // 64-row half
    const int wn   = wid >> 1;         // 64-col half
    const int n0   = blockIdx.x << 7;
    const int m0   = blockIdx.y << 7;

    const uint32_t sbase = smem_u32(smem_buf);

    // ---- cp.async writers (128 threads) ----
    const float* gA = A + (size_t)(m0 + (tid >> 2)) * 512 + ((tid & 3) << 2);
    const uint32_t awb = sbase + (uint32_t)((tid >> 2) * 112 + ((tid & 3) << 4));
    const float* gB = B + (size_t)(tid >> 5) * Ntot + n0 + ((tid & 31) << 2);
    const uint32_t bwb = sbase + B_OFF_B +
                         (uint32_t)((tid >> 5) * 544 + ((tid & 31) << 4));
    const size_t bStepL = (size_t)4 * Ntot;     // +4 k-rows
    const size_t bStepC = (size_t)16 * Ntot;    // +16 k-rows per chunk

    // ---- readers ----
    const uint32_t aRd = sbase +
        (uint32_t)((wm * 64 + (lane & 15)) * 112 + ((lane >> 4) << 4));
    const uint32_t bRd = sbase + B_OFF_B +
        (uint32_t)(t * 544 + ((wn * 64 + g) << 2));

    float acc[4][8][4];
#pragma unroll
    for (int mt = 0; mt < 4; ++mt)
#pragma unroll
        for (int nt = 0; nt < 8; ++nt)
#pragma unroll
            for (int e = 0; e < 4; ++e) acc[mt][nt][e] = 0.0f;

    auto LOAD_CHUNK = [&](int c, int stg) {
        const float* pA = gA + c * 16;
        const float* pB = gB + (size_t)c * bStepC;
        const uint32_t aw = awb + stg * STG_BYTES;
        const uint32_t bw = bwb + stg * STG_BYTES;
#pragma unroll
        for (int l = 0; l < 4; ++l)
            CP_ASYNC16(aw + l * 3584, pA + (size_t)(32 * l) * 512);
#pragma unroll
        for (int l = 0; l < 4; ++l)
            CP_ASYNC16(bw + l * 2176, pB + (size_t)l * bStepL);
        CP_COMMIT();
    };

    auto COMPUTE = [&](int stg) {
        const uint32_t ab = aRd + stg * STG_BYTES;
        const uint32_t bb = bRd + stg * STG_BYTES;
#pragma unroll
        for (int s = 0; s < 2; ++s) {
            uint32_t af[4][4];
#pragma unroll
            for (int mt = 0; mt < 4; ++mt) {
                uint32_t r0, r1, r2, r3;
                LDSM4(r0, r1, r2, r3, ab + mt * 1792 + s * 32);
                af[mt][0] = f2tf32(__uint_as_float(r0));
                af[mt][1] = f2tf32(__uint_as_float(r1));
                af[mt][2] = f2tf32(__uint_as_float(r2));
                af[mt][3] = f2tf32(__uint_as_float(r3));
            }
            uint32_t bf[8][2];
#pragma unroll
            for (int nt = 0; nt < 8; ++nt) {
                uint32_t a0 = bb + s * 4352 + nt * 32;
                bf[nt][0] = f2tf32(lds_f32(a0));
                bf[nt][1] = f2tf32(lds_f32(a0 + 2176));
            }
#pragma unroll
            for (int mt = 0; mt < 4; ++mt)
#pragma unroll
                for (int nt = 0; nt < 8; ++nt)
                    mma_tf32(acc[mt][nt], af[mt], bf[nt]);
        }
    };

    // ---- prologue: chunks 0,1 -> stages 0,1 ----
    LOAD_CHUNK(0, 0);
    LOAD_CHUNK(1, 1);
    asm volatile("cp.async.wait_group 1;" ::: "memory");   // chunk 0 ready
    __syncthreads();

    // ---- mainloop: one barrier per chunk ----
    int sr = 0;                        // stage holding chunk c
    for (int c = 0; c < 32; ++c) {
        // stage (c+2)%3 == stage of chunk c-1: fully consumed before the
        // barrier at the end of the previous iteration => safe to overwrite.
        if (c + 2 < 32) {
            int sw = sr + 2;
            if (sw >= 3) sw -= 3;
            LOAD_CHUNK(c + 2, sw);
        }
        COMPUTE(sr);
        if (c + 2 < 32)
            asm volatile("cp.async.wait_group 1;" ::: "memory"); // chunk c+1 ready
        else
            asm volatile("cp.async.wait_group 0;" ::: "memory");
        __syncthreads();
        sr = (sr == 2) ? 0 : sr + 1;
    }

    // ---- epilogue ----
    float2 bv[8];
#pragma unroll
    for (int nt = 0; nt < 8; ++nt) {
        const int col = n0 + wn * 64 + nt * 8 + 2 * t;
        bv[nt].x = bias[col];
        bv[nt].y = bias[col + 1];
    }
#pragma unroll
    for (int mt = 0; mt < 4; ++mt) {
        const int mr = m0 + wm * 64 + mt * 16;
#pragma unroll
        for (int nt = 0; nt < 8; ++nt) {
            const int col = n0 + wn * 64 + nt * 8 + 2 * t;
            float2 o0, o1;
            o0.x = acc[mt][nt][0] + bv[nt].x;
            o0.y = acc[mt][nt][1] + bv[nt].y;
            o1.x = acc[mt][nt][2] + bv[nt].x;
            o1.y = acc[mt][nt][3] + bv[nt].y;
            *(float2*)(C + (size_t)(mr + g) * Ntot + col)     = o0;
            *(float2*)(C + (size_t)(mr + g + 8) * Ntot + col) = o1;
        }
    }
}

// ---------------------------------------------------------------------------
// Attention: one block (256 threads) per (window w in [0,1024), head in [0,8)).
// ---------------------------------------------------------------------------
__global__ __launch_bounds__(256)
void attn_kernel() {
    const int blk = blockIdx.x;
    const int hh  = blk & 7;
    const int w   = blk >> 3;
    const int b   = w >> 8;
    const int rem = w & 255;
    const int wij = rem >> 2;
    const int d   = rem & 3;
    const int wi  = wij >> 3;
    const int wj  = wij & 7;

    __shared__ float bufA[64][66];
    __shared__ float bufB[64][66];
    __shared__ int   st[64];
    __shared__ int   sband[64];

    const int tid = threadIdx.x;

    if (tid < 64) {
        int n = tid;
        int gi = wi * 16 + ((n >> 3) << 1) + (d >> 1);
        int gj = wj * 16 + ((n & 7) << 1) + (d & 1);
        int h  = (gi + 4) & 127;
        int wc = (gj + 4) & 127;
        st[n] = (b << 14) | (h << 7) | wc;
        sband[n] = (gi < 120) ? 0 : ((gi < 124) ? 1 : 2);
    }
    __syncthreads();

    const int row  = tid >> 2;
    const int quad = tid & 3;
    const int t    = st[row];
    const float* qg = g_qv + (size_t)t * 1024 + hh * 64 + quad * 16;
    const float* kg = g_k  + (size_t)t * 512  + hh * 64 + quad * 16;
    const float fh = (float)(row >> 3);
    const float fw = (float)(row & 7);
    const float L  = 13.287712379549449f / 16.0f;

#pragma unroll
    for (int f = 0; f < 4; ++f) {
        const int c0 = quad * 16 + f * 4;
        float4 q4 = *(const float4*)(qg + f * 4);
        float4 k4 = *(const float4*)(kg + f * 4);
        float rq[4] = {q4.x, q4.y, q4.z, q4.w};
        float rk[4] = {k4.x, k4.y, k4.z, k4.w};
#pragma unroll
        for (int e = 0; e < 2; ++e) {
            int p = (c0 >> 1) + e;
            float coord = (p < 16) ? fh : fw;
            float inv = exp2f(-(float)(p & 15) * L);
            float ang = coord * inv;
            float sv, cv;
            sincosf(ang, &sv, &cv);
            float x1 = rq[2 * e], x2 = rq[2 * e + 1];
            rq[2 * e]     = x1 * cv - x2 * sv;
            rq[2 * e + 1] = x1 * sv + x2 * cv;
            x1 = rk[2 * e]; x2 = rk[2 * e + 1];
            rk[2 * e]     = x1 * cv - x2 * sv;
            rk[2 * e + 1] = x1 * sv + x2 * cv;
        }
#pragma unroll
        for (int e2 = 0; e2 < 4; ++e2) {
            bufA[row][c0 + e2] = rq[e2];
            bufB[c0 + e2][row] = rk[e2];
        }
    }
    __syncthreads();

    const int ty = tid >> 4;
    const int tx = tid & 15;
    float S[4][4];
#pragma unroll
    for (int i = 0; i < 4; ++i)
#pragma unroll
        for (int j = 0; j < 4; ++j) S[i][j] = 0.0f;

#pragma unroll 8
    for (int kk = 0; kk < 64; ++kk) {
        float a[4], bb[4];
#pragma unroll
        for (int i = 0; i < 4; ++i) a[i]  = bufA[ty * 4 + i][kk];
#pragma unroll
        for (int j = 0; j < 4; ++j) bb[j] = bufB[kk][tx * 4 + j];
#pragma unroll
        for (int i = 0; i < 4; ++i)
#pragma unroll
            for (int j = 0; j < 4; ++j)
                S[i][j] = fmaf(a[i], bb[j], S[i][j]);
    }

    const float scale = 0.125f;
    int bandr[4], bandc[4];
#pragma unroll
    for (int i = 0; i < 4; ++i) bandr[i] = sband[ty * 4 + i];
#pragma unroll
    for (int j = 0; j < 4; ++j) bandc[j] = sband[tx * 4 + j];

#pragma unroll
    for (int i = 0; i < 4; ++i)
#pragma unroll
        for (int j = 0; j < 4; ++j)
            S[i][j] = S[i][j] * scale + ((bandr[i] == bandc[j]) ? 0.0f : -1e9f);

#pragma unroll
    for (int i = 0; i < 4; ++i) {
        float m = fmaxf(fmaxf(S[i][0], S[i][1]), fmaxf(S[i][2], S[i][3]));
#pragma unroll
        for (int off = 1; off < 16; off <<= 1)
            m = fmaxf(m, __shfl_xor_sync(0xffffffffu, m, off));
        float s = 0.0f;
#pragma unroll
        for (int j = 0; j < 4; ++j) {
            S[i][j] = expf(S[i][j] - m);
            s += S[i][j];
        }
#pragma unroll
        for (int off = 1; off < 16; off <<= 1)
            s += __shfl_xor_sync(0xffffffffu, s, off);
        float r = 1.0f / s;
#pragma unroll
        for (int j = 0; j < 4; ++j) S[i][j] *= r;
    }

    __syncthreads();

#pragma unroll
    for (int i = 0; i < 4; ++i)
#pragma unroll
        for (int j = 0; j < 4; ++j)
            bufB[ty * 4 + i][tx * 4 + j] = S[i][j];

    const float* vg = g_qv + (size_t)t * 1024 + 512 + hh * 64 + quad * 16;
#pragma unroll
    for (int f = 0; f < 4; ++f) {
        float4 v4 = *(const float4*)(vg + f * 4);
        int c0 = quad * 16 + f * 4;
        bufA[row][c0 + 0] = v4.x;
        bufA[row][c0 + 1] = v4.y;
        bufA[row][c0 + 2] = v4.z;
        bufA[row][c0 + 3] = v4.w;
    }
    __syncthreads();

    float O[4][4];
#pragma unroll
    for (int i = 0; i < 4; ++i)
#pragma unroll
        for (int j = 0; j < 4; ++j) O[i][j] = 0.0f;

#pragma unroll 8
    for (int kk = 0; kk < 64; ++kk) {
        float a[4], bb[4];
#pragma unroll
        for (int i = 0; i < 4; ++i) a[i]  = bufB[ty * 4 + i][kk];
#pragma unroll
        for (int j = 0; j < 4; ++j) bb[j] = bufA[kk][tx * 4 + j];
#pragma unroll
        for (int i = 0; i < 4; ++i)
#pragma unroll
            for (int j = 0; j < 4; ++j)
                O[i][j] = fmaf(a[i], bb[j], O[i][j]);
    }

#pragma unroll
    for (int i = 0; i < 4; ++i) {
        int tr = st[ty * 4 + i];
        float4 o4;
        o4.x = O[i][0]; o4.y = O[i][1]; o4.z = O[i][2]; o4.w = O[i][3];
        *(float4*)(g_o + (size_t)tr * 512 + hh * 64 + tx * 4) = o4;
    }
}

// ---------------------------------------------------------------------------
extern "C" void kernel_launch(void* const* d_in, const int* in_sizes, int n_in,
                              void* d_out, int out_size) {
    (void)in_sizes; (void)n_in; (void)out_size;
    const float* x      = (const float*)d_in[0];
    const float* cross  = (const float*)d_in[1];
    const float* qv_w   = (const float*)d_in[2];
    const float* qv_b   = (const float*)d_in[3];
    const float* k_w    = (const float*)d_in[4];
    const float* k_b    = (const float*)d_in[5];
    const float* proj_w = (const float*)d_in[6];
    const float* proj_b = (const float*)d_in[7];
    float* out = (float*)d_out;

    float *qv_ptr = nullptr, *k_ptr = nullptr, *o_ptr = nullptr;
    cudaGetSymbolAddress((void**)&qv_ptr, g_qv);
    cudaGetSymbolAddress((void**)&k_ptr,  g_k);
    cudaGetSymbolAddress((void**)&o_ptr,  g_o);

    // 1) QV = x @ qv_w + qv_b        (65536 x 1024)
    mm_tf32<<<dim3(8, 512), 128>>>(x, qv_w, qv_b, qv_ptr, 1024);
    // 2) K  = cross @ k_w + k_b      (65536 x 512)
    mm_tf32<<<dim3(4, 512), 128>>>(cross, k_w, k_b, k_ptr, 512);
    // 3) windowed attention -> g_o
    attn_kernel<<<8192, 256>>>();
    // 4) out = g_o @ proj_w + proj_b (65536 x 512)
    mm_tf32<<<dim3(4, 512), 128>>>(o_ptr, proj_w, proj_b, out, 512);
}

// round 14
// speedup vs baseline: 1.0812x; 1.0812x over previous
#include <cuda_runtime.h>
#include <math.h>
#include <stdint.h>

// ---------------------------------------------------------------------------
// SD_attn_Cross on GB300 (compute_103 => mma.sync tf32 path).
// GEMM: block 128x128, 4 warps (2m x 2n), warp tile 64x64, BK=16,
// cp.async double buffer, ldmatrix A fragments, padded conflict-free smem.
// Weights pre-rounded to tf32 (B side cvt-free); attention stores tf32-rounded
// g_o so the proj GEMM is fully cvt-free in its mainloop.
// ---------------------------------------------------------------------------

#define TOKENS 65536

__device__ float g_qv[(size_t)TOKENS * 1024];
__device__ float g_k [(size_t)TOKENS * 512];
__device__ float g_o [(size_t)TOKENS * 512];
// tf32-rounded weights: qv_w (512x1024) | k_w (512x512) | proj_w (512x512)
__device__ float g_wr[512 * 1024 + 512 * 512 + 512 * 512];

// ------------------------------ PTX helpers --------------------------------
__device__ __forceinline__ uint32_t smem_u32(const void* p) {
    uint32_t a;
    asm("{ .reg .u64 t; cvta.to.shared.u64 t, %1; cvt.u32.u64 %0, t; }"
        : "=r"(a) : "l"(p));
    return a;
}
#define CP_ASYNC16(sdst, gsrc) \
    asm volatile("cp.async.cg.shared.global [%0], [%1], 16;" :: "r"(sdst), "l"(gsrc) : "memory")
#define CP_COMMIT() asm volatile("cp.async.commit_group;" ::: "memory")

__device__ __forceinline__ uint32_t f2tf32(float x) {
    uint32_t u;
    asm("cvt.rna.tf32.f32 %0, %1;" : "=r"(u) : "f"(x));
    return u;
}
__device__ __forceinline__ void mma_tf32(float c[4], const uint32_t a[4],
                                         const uint32_t b[2]) {
    asm volatile(
        "mma.sync.aligned.m16n8k8.row.col.f32.tf32.tf32.f32 "
        "{%0,%1,%2,%3}, {%4,%5,%6,%7}, {%8,%9}, {%0,%1,%2,%3};"
        : "+f"(c[0]), "+f"(c[1]), "+f"(c[2]), "+f"(c[3])
        : "r"(a[0]), "r"(a[1]), "r"(a[2]), "r"(a[3]), "r"(b[0]), "r"(b[1]));
}
#define LDSM4(r0, r1, r2, r3, addr)                                           \
    asm volatile("ldmatrix.sync.aligned.m8n8.x4.shared.b16 {%0,%1,%2,%3},[%4];" \
                 : "=r"(r0), "=r"(r1), "=r"(r2), "=r"(r3) : "r"(addr))
__device__ __forceinline__ uint32_t lds_u32(uint32_t addr) {
    uint32_t v;
    asm volatile("ld.shared.b32 %0, [%1];" : "=r"(v) : "r"(addr));
    return v;
}

// --------------------- tf32 rounding pre-pass (weights) --------------------
__global__ void round_tf32(const float* __restrict__ src,
                           float* __restrict__ dst, int n4) {
    int i = blockIdx.x * blockDim.x + threadIdx.x;
    if (i < n4) {
        float4 v = ((const float4*)src)[i];
        float4 o;
        o.x = __uint_as_float(f2tf32(v.x));
        o.y = __uint_as_float(f2tf32(v.y));
        o.z = __uint_as_float(f2tf32(v.z));
        o.w = __uint_as_float(f2tf32(v.w));
        ((float4*)dst)[i] = o;
    }
}

// ------------------------- tf32 tensor-core GEMM ---------------------------
// C[m,n] = sum_k A[m,k]*B[k,n] + bias[n].  K=512 fixed, M,N multiples of 128.
// B must be pre-rounded to tf32.  A is cvt'd in-loop iff CVT_A.
// Smem stage: A 128 rows x stride 28 fl (112B, 16B-aligned, LDSM-conflict-free)
//             B  16 rows x stride 136 fl (bank g+8t distinct => conflict-free)
#define A_STRIDE 28
#define B_STRIDE 136
#define A_FLOATS (128 * A_STRIDE)              // 3584
#define STG_FLOATS (A_FLOATS + 16 * B_STRIDE)  // 5760
#define STG_BYTES (STG_FLOATS * 4)             // 23040
#define B_OFF_B (A_FLOATS * 4)                 // 14336

template <bool CVT_A>
__global__ __launch_bounds__(128)
void mm_tf32(const float* __restrict__ A, const float* __restrict__ B,
             const float* __restrict__ bias, float* __restrict__ C, int Ntot) {
    __shared__ __align__(16) float smem_buf[2][STG_FLOATS];

    const int tid  = threadIdx.x;
    const int lane = tid & 31;
    const int wid  = tid >> 5;
    const int g    = lane >> 2;
    const int t    = lane & 3;
    const int wm   = wid & 1;          // 64-row half
    const int wn   = wid >> 1;         // 64-col half
    const int n0   = blockIdx.x << 7;
    const int m0   = blockIdx.y << 7;

    const uint32_t sbase = smem_u32(smem_buf);

    // ---- cp.async writers (128 threads) ----
    const float* gA = A + (size_t)(m0 + (tid >> 2)) * 512 + ((tid & 3) << 2);
    const uint32_t awb = sbase + (uint32_t)((tid >> 2) * 112 + ((tid & 3) << 4));
    const float* gB = B + (size_t)(tid >> 5) * Ntot + n0 + ((tid & 31) << 2);
    const uint32_t bwb = sbase + B_OFF_B +
                         (uint32_t)((tid >> 5) * 544 + ((tid & 31) << 4));
    const size_t bStepL = (size_t)4 * Ntot;     // +4 k-rows
    const size_t bStepC = (size_t)16 * Ntot;    // +16 k-rows per chunk

    // ---- readers ----
    const uint32_t aRd = sbase +
        (uint32_t)((wm * 64 + (lane & 15)) * 112 + ((lane >> 4) << 4));
    const uint32_t bRd = sbase + B_OFF_B +
        (uint32_t)(t * 544 + ((wn * 64 + g) << 2));

    float acc[4][8][4];
#pragma unroll
    for (int mt = 0; mt < 4; ++mt)
#pragma unroll
        for (int nt = 0; nt < 8; ++nt)
#pragma unroll
            for (int e = 0; e < 4; ++e) acc[mt][nt][e] = 0.0f;

    auto LOAD_CHUNK = [&](int c, int stg) {
        const float* pA = gA + c * 16;
        const float* pB = gB + (size_t)c * bStepC;
        const uint32_t aw = awb + stg * STG_BYTES;
        const uint32_t bw = bwb + stg * STG_BYTES;
#pragma unroll
        for (int l = 0; l < 4; ++l)
            CP_ASYNC16(aw + l * 3584, pA + (size_t)(32 * l) * 512);
#pragma unroll
        for (int l = 0; l < 4; ++l)
            CP_ASYNC16(bw + l * 2176, pB + (size_t)l * bStepL);
        CP_COMMIT();
    };

    // ---- prologue: chunk 0 -> stage 0 ----
    LOAD_CHUNK(0, 0);

    for (int c = 0; c < 32; ++c) {
        const int cur = c & 1;
        if (c < 31) {
            LOAD_CHUNK(c + 1, cur ^ 1);
            asm volatile("cp.async.wait_group 1;" ::: "memory");
        } else {
            asm volatile("cp.async.wait_group 0;" ::: "memory");
        }
        __syncthreads();

        const uint32_t ab = aRd + cur * STG_BYTES;
        const uint32_t bb = bRd + cur * STG_BYTES;
#pragma unroll
        for (int s = 0; s < 2; ++s) {
            uint32_t af[4][4];
#pragma unroll
            for (int mt = 0; mt < 4; ++mt) {
                uint32_t r0, r1, r2, r3;
                LDSM4(r0, r1, r2, r3, ab + mt * 1792 + s * 32);
                if (CVT_A) {
                    af[mt][0] = f2tf32(__uint_as_float(r0));
                    af[mt][1] = f2tf32(__uint_as_float(r1));
                    af[mt][2] = f2tf32(__uint_as_float(r2));
                    af[mt][3] = f2tf32(__uint_as_float(r3));
                } else {
                    af[mt][0] = r0; af[mt][1] = r1;
                    af[mt][2] = r2; af[mt][3] = r3;
                }
            }
            uint32_t bf[8][2];
#pragma unroll
            for (int nt = 0; nt < 8; ++nt) {
                uint32_t a0 = bb + s * 4352 + nt * 32;
                bf[nt][0] = lds_u32(a0);
                bf[nt][1] = lds_u32(a0 + 2176);
            }
#pragma unroll
            for (int mt = 0; mt < 4; ++mt)
#pragma unroll
                for (int nt = 0; nt < 8; ++nt)
                    mma_tf32(acc[mt][nt], af[mt], bf[nt]);
        }
        __syncthreads();
    }

    // ---- epilogue ----
    float2 bv[8];
#pragma unroll
    for (int nt = 0; nt < 8; ++nt) {
        const int col = n0 + wn * 64 + nt * 8 + 2 * t;
        bv[nt].x = bias[col];
        bv[nt].y = bias[col + 1];
    }
#pragma unroll
    for (int mt = 0; mt < 4; ++mt) {
        const int mr = m0 + wm * 64 + mt * 16;
#pragma unroll
        for (int nt = 0; nt < 8; ++nt) {
            const int col = n0 + wn * 64 + nt * 8 + 2 * t;
            float2 o0, o1;
            o0.x = acc[mt][nt][0] + bv[nt].x;
            o0.y = acc[mt][nt][1] + bv[nt].y;
            o1.x = acc[mt][nt][2] + bv[nt].x;
            o1.y = acc[mt][nt][3] + bv[nt].y;
            *(float2*)(C + (size_t)(mr + g) * Ntot + col)     = o0;
            *(float2*)(C + (size_t)(mr + g + 8) * Ntot + col) = o1;
        }
    }
}

// ---------------------------------------------------------------------------
// Attention: one block (256 threads) per (window w in [0,1024), head in [0,8)).
// Output is rounded to tf32 so the proj GEMM can skip in-loop conversion.
// ---------------------------------------------------------------------------
__global__ __launch_bounds__(256)
void attn_kernel() {
    const int blk = blockIdx.x;
    const int hh  = blk & 7;
    const int w   = blk >> 3;
    const int b   = w >> 8;
    const int rem = w & 255;
    const int wij = rem >> 2;
    const int d   = rem & 3;
    const int wi  = wij >> 3;
    const int wj  = wij & 7;

    __shared__ float bufA[64][66];
    __shared__ float bufB[64][66];
    __shared__ int   st[64];
    __shared__ int   sband[64];

    const int tid = threadIdx.x;

    if (tid < 64) {
        int n = tid;
        int gi = wi * 16 + ((n >> 3) << 1) + (d >> 1);
        int gj = wj * 16 + ((n & 7) << 1) + (d & 1);
        int h  = (gi + 4) & 127;
        int wc = (gj + 4) & 127;
        st[n] = (b << 14) | (h << 7) | wc;
        sband[n] = (gi < 120) ? 0 : ((gi < 124) ? 1 : 2);
    }
    __syncthreads();

    const int row  = tid >> 2;
    const int quad = tid & 3;
    const int t    = st[row];
    const float* qg = g_qv + (size_t)t * 1024 + hh * 64 + quad * 16;
    const float* kg = g_k  + (size_t)t * 512  + hh * 64 + quad * 16;
    const float fh = (float)(row >> 3);
    const float fw = (float)(row & 7);
    const float L  = 13.287712379549449f / 16.0f;

#pragma unroll
    for (int f = 0; f < 4; ++f) {
        const int c0 = quad * 16 + f * 4;
        float4 q4 = *(const float4*)(qg + f * 4);
        float4 k4 = *(const float4*)(kg + f * 4);
        float rq[4] = {q4.x, q4.y, q4.z, q4.w};
        float rk[4] = {k4.x, k4.y, k4.z, k4.w};
#pragma unroll
        for (int e = 0; e < 2; ++e) {
            int p = (c0 >> 1) + e;
            float coord = (p < 16) ? fh : fw;
            float inv = exp2f(-(float)(p & 15) * L);
            float ang = coord * inv;
            float sv, cv;
            sincosf(ang, &sv, &cv);
            float x1 = rq[2 * e], x2 = rq[2 * e + 1];
            rq[2 * e]     = x1 * cv - x2 * sv;
            rq[2 * e + 1] = x1 * sv + x2 * cv;
            x1 = rk[2 * e]; x2 = rk[2 * e + 1];
            rk[2 * e]     = x1 * cv - x2 * sv;
            rk[2 * e + 1] = x1 * sv + x2 * cv;
        }
#pragma unroll
        for (int e2 = 0; e2 < 4; ++e2) {
            bufA[row][c0 + e2] = rq[e2];
            bufB[c0 + e2][row] = rk[e2];
        }
    }
    __syncthreads();

    const int ty = tid >> 4;
    const int tx = tid & 15;
    float S[4][4];
#pragma unroll
    for (int i = 0; i < 4; ++i)
#pragma unroll
        for (int j = 0; j < 4; ++j) S[i][j] = 0.0f;

#pragma unroll 8
    for (int kk = 0; kk < 64; ++kk) {
        float a[4], bb[4];
#pragma unroll
        for (int i = 0; i < 4; ++i) a[i]  = bufA[ty * 4 + i][kk];
#pragma unroll
        for (int j = 0; j < 4; ++j) bb[j] = bufB[kk][tx * 4 + j];
#pragma unroll
        for (int i = 0; i < 4; ++i)
#pragma unroll
            for (int j = 0; j < 4; ++j)
                S[i][j] = fmaf(a[i], bb[j], S[i][j]);
    }

    const float scale = 0.125f;
    int bandr[4], bandc[4];
#pragma unroll
    for (int i = 0; i < 4; ++i) bandr[i] = sband[ty * 4 + i];
#pragma unroll
    for (int j = 0; j < 4; ++j) bandc[j] = sband[tx * 4 + j];

#pragma unroll
    for (int i = 0; i < 4; ++i)
#pragma unroll
        for (int j = 0; j < 4; ++j)
            S[i][j] = S[i][j] * scale + ((bandr[i] == bandc[j]) ? 0.0f : -1e9f);

#pragma unroll
    for (int i = 0; i < 4; ++i) {
        float m = fmaxf(fmaxf(S[i][0], S[i][1]), fmaxf(S[i][2], S[i][3]));
#pragma unroll
        for (int off = 1; off < 16; off <<= 1)
            m = fmaxf(m, __shfl_xor_sync(0xffffffffu, m, off));
        float s = 0.0f;
#pragma unroll
        for (int j = 0; j < 4; ++j) {
            S[i][j] = expf(S[i][j] - m);
            s += S[i][j];
        }
#pragma unroll
        for (int off = 1; off < 16; off <<= 1)
            s += __shfl_xor_sync(0xffffffffu, s, off);
        float r = 1.0f / s;
#pragma unroll
        for (int j = 0; j < 4; ++j) S[i][j] *= r;
    }

    __syncthreads();

#pragma unroll
    for (int i = 0; i < 4; ++i)
#pragma unroll
        for (int j = 0; j < 4; ++j)
            bufB[ty * 4 + i][tx * 4 + j] = S[i][j];

    const float* vg = g_qv + (size_t)t * 1024 + 512 + hh * 64 + quad * 16;
#pragma unroll
    for (int f = 0; f < 4; ++f) {
        float4 v4 = *(const float4*)(vg + f * 4);
        int c0 = quad * 16 + f * 4;
        bufA[row][c0 + 0] = v4.x;
        bufA[row][c0 + 1] = v4.y;
        bufA[row][c0 + 2] = v4.z;
        bufA[row][c0 + 3] = v4.w;
    }
    __syncthreads();

    float O[4][4];
#pragma unroll
    for (int i = 0; i < 4; ++i)
#pragma unroll
        for (int j = 0; j < 4; ++j) O[i][j] = 0.0f;

#pragma unroll 8
    for (int kk = 0; kk < 64; ++kk) {
        float a[4], bb[4];
#pragma unroll
        for (int i = 0; i < 4; ++i) a[i]  = bufB[ty * 4 + i][kk];
#pragma unroll
        for (int j = 0; j < 4; ++j) bb[j] = bufA[kk][tx * 4 + j];
#pragma unroll
        for (int i = 0; i < 4; ++i)
#pragma unroll
            for (int j = 0; j < 4; ++j)
                O[i][j] = fmaf(a[i], bb[j], O[i][j]);
    }

#pragma unroll
    for (int i = 0; i < 4; ++i) {
        int tr = st[ty * 4 + i];
        float4 o4;
        o4.x = __uint_as_float(f2tf32(O[i][0]));
        o4.y = __uint_as_float(f2tf32(O[i][1]));
        o4.z = __uint_as_float(f2tf32(O[i][2]));
        o4.w = __uint_as_float(f2tf32(O[i][3]));
        *(float4*)(g_o + (size_t)tr * 512 + hh * 64 + tx * 4) = o4;
    }
}

// ---------------------------------------------------------------------------
extern "C" void kernel_launch(void* const* d_in, const int* in_sizes, int n_in,
                              void* d_out, int out_size) {
    (void)in_sizes; (void)n_in; (void)out_size;
    const float* x      = (const float*)d_in[0];
    const float* cross  = (const float*)d_in[1];
    const float* qv_w   = (const float*)d_in[2];
    const float* qv_b   = (const float*)d_in[3];
    const float* k_w    = (const float*)d_in[4];
    const float* k_b    = (const float*)d_in[5];
    const float* proj_w = (const float*)d_in[6];
    const float* proj_b = (const float*)d_in[7];
    float* out = (float*)d_out;

    float *qv_ptr = nullptr, *k_ptr = nullptr, *o_ptr = nullptr, *wr = nullptr;
    cudaGetSymbolAddress((void**)&qv_ptr, g_qv);
    cudaGetSymbolAddress((void**)&k_ptr,  g_k);
    cudaGetSymbolAddress((void**)&o_ptr,  g_o);
    cudaGetSymbolAddress((void**)&wr,     g_wr);
    float* wr_qv = wr;                  // 512x1024
    float* wr_k  = wr + 512 * 1024;     // 512x512
    float* wr_p  = wr_k + 512 * 512;    // 512x512

    // 0) pre-round weights to tf32 (numerically identical to in-loop cvt)
    round_tf32<<<512, 256>>>(qv_w,   wr_qv, 512 * 1024 / 4);
    round_tf32<<<256, 256>>>(k_w,    wr_k,  512 * 512 / 4);
    round_tf32<<<256, 256>>>(proj_w, wr_p,  512 * 512 / 4);

    // 1) QV = x @ qv_w + qv_b        (65536 x 1024)
    mm_tf32<true><<<dim3(8, 512), 128>>>(x, wr_qv, qv_b, qv_ptr, 1024);
    // 2) K  = cross @ k_w + k_b      (65536 x 512)
    mm_tf32<true><<<dim3(4, 512), 128>>>(cross, wr_k, k_b, k_ptr, 512);
    // 3) windowed attention -> g_o (tf32-rounded)
    attn_kernel<<<8192, 256>>>();
    // 4) out = g_o @ proj_w + proj_b (65536 x 512)
    mm_tf32<false><<<dim3(4, 512), 128>>>(o_ptr, wr_p, proj_b, out, 512);
}